// round 1
// baseline (speedup 1.0000x reference)
#include <cuda_runtime.h>

#define Bn 8192
#define Fn 4096
#define Kn 64
#define TM 64          // rows per CTA
#define TF 32          // f-depth per smem tile
#define NTHREADS 256
#define XS_STRIDE 68   // 64 rows + pad, multiple of 4 for float4 alignment

__device__ float d_s[Fn];   // s[f] = sum_k v[f][k]^2

__global__ void compute_s_kernel(const float* __restrict__ v) {
    int f = blockIdx.x * blockDim.x + threadIdx.x;
    if (f < Fn) {
        const float4* vp = (const float4*)(v + (size_t)f * Kn);
        float t = 0.f;
#pragma unroll
        for (int k4 = 0; k4 < Kn / 4; k4++) {
            float4 a = vp[k4];
            t += a.x * a.x + a.y * a.y + a.z * a.z + a.w * a.w;
        }
        d_s[f] = t;
    }
}

__global__ void __launch_bounds__(NTHREADS) fm_kernel(
    const float* __restrict__ x, const float* __restrict__ v,
    float* __restrict__ out)
{
    __shared__ float x_s[2][TF][XS_STRIDE];  // transposed, XOR-swizzled: [f][row ^ 8*(f>>3)]
    __shared__ float v_s[2][TF][Kn];
    __shared__ float xsq_s[4][TM];

    const int tid = threadIdx.x;
    // compute mapping: 16 (k) x 16 (row) thread grid, 4x4 per-thread tile
    const int tx = tid & 15;          // k:   4*tx .. 4*tx+3
    const int ty = tid >> 4;          // row: 4*ty .. 4*ty+3
    // x loader mapping: row = tid>>2 (0..63), q = tid&3 selects f-octet
    const int lrow = tid >> 2;
    const int lq   = tid & 3;
    const int lcol = lrow ^ (lq << 3);  // swizzled column (conflict-free STS)
    // v loader mapping
    const int vf   = tid >> 4;        // 0..15
    const int vseg = tid & 15;        // 0..15

    const int row0 = blockIdx.x * TM;

    const float* xg  = x + (size_t)(row0 + lrow) * Fn + 8 * lq;
    const float* vg  = v + (size_t)vf * Kn + 4 * vseg;
    const float* sg  = d_s + 8 * lq;

    float acc[4][4];
#pragma unroll
    for (int i = 0; i < 4; i++)
#pragma unroll
        for (int j = 0; j < 4; j++) acc[i][j] = 0.f;

    float xsq = 0.f;

    float4 xa, xb, va, vb, sa, sb;

    // ---- prefetch tile 0 ----
    xa = *(const float4*)(xg);
    xb = *(const float4*)(xg + 4);
    va = *(const float4*)(vg);
    vb = *(const float4*)(vg + 16 * Kn);
    sa = *(const float4*)(sg);
    sb = *(const float4*)(sg + 4);

    // ---- store tile 0 into buffer 0 ----
    {
        x_s[0][8 * lq + 0][lcol] = xa.x;
        x_s[0][8 * lq + 1][lcol] = xa.y;
        x_s[0][8 * lq + 2][lcol] = xa.z;
        x_s[0][8 * lq + 3][lcol] = xa.w;
        x_s[0][8 * lq + 4][lcol] = xb.x;
        x_s[0][8 * lq + 5][lcol] = xb.y;
        x_s[0][8 * lq + 6][lcol] = xb.z;
        x_s[0][8 * lq + 7][lcol] = xb.w;
        *(float4*)&v_s[0][vf][4 * vseg]      = va;
        *(float4*)&v_s[0][vf + 16][4 * vseg] = vb;
        xsq += xa.x * xa.x * sa.x + xa.y * xa.y * sa.y
             + xa.z * xa.z * sa.z + xa.w * xa.w * sa.w
             + xb.x * xb.x * sb.x + xb.y * xb.y * sb.y
             + xb.z * xb.z * sb.z + xb.w * xb.w * sb.w;
    }
    __syncthreads();

    const int nT = Fn / TF;  // 128 tiles
    for (int t = 0; t < nT; t++) {
        const int cur = t & 1;

        // prefetch tile t+1 into registers (overlaps with compute)
        if (t + 1 < nT) {
            const float* xp = xg + (size_t)(t + 1) * TF;
            xa = *(const float4*)(xp);
            xb = *(const float4*)(xp + 4);
            const float* vp = vg + (size_t)(t + 1) * TF * Kn;
            va = *(const float4*)(vp);
            vb = *(const float4*)(vp + 16 * Kn);
            const float* sp = sg + (t + 1) * TF;
            sa = *(const float4*)(sp);
            sb = *(const float4*)(sp + 4);
        }

        // ---- compute on current buffer ----
#pragma unroll
        for (int f = 0; f < TF; f++) {
            const int xcol = (4 * ty) ^ (f & 24);   // (f>>3)<<3, compile-time per iter
            float4 xv = *(const float4*)&x_s[cur][f][xcol];
            float4 vv = *(const float4*)&v_s[cur][f][4 * tx];
            acc[0][0] += xv.x * vv.x; acc[0][1] += xv.x * vv.y;
            acc[0][2] += xv.x * vv.z; acc[0][3] += xv.x * vv.w;
            acc[1][0] += xv.y * vv.x; acc[1][1] += xv.y * vv.y;
            acc[1][2] += xv.y * vv.z; acc[1][3] += xv.y * vv.w;
            acc[2][0] += xv.z * vv.x; acc[2][1] += xv.z * vv.y;
            acc[2][2] += xv.z * vv.z; acc[2][3] += xv.z * vv.w;
            acc[3][0] += xv.w * vv.x; acc[3][1] += xv.w * vv.y;
            acc[3][2] += xv.w * vv.z; acc[3][3] += xv.w * vv.w;
        }

        // ---- store tile t+1 into the other buffer ----
        if (t + 1 < nT) {
            const int nb = (t + 1) & 1;
            x_s[nb][8 * lq + 0][lcol] = xa.x;
            x_s[nb][8 * lq + 1][lcol] = xa.y;
            x_s[nb][8 * lq + 2][lcol] = xa.z;
            x_s[nb][8 * lq + 3][lcol] = xa.w;
            x_s[nb][8 * lq + 4][lcol] = xb.x;
            x_s[nb][8 * lq + 5][lcol] = xb.y;
            x_s[nb][8 * lq + 6][lcol] = xb.z;
            x_s[nb][8 * lq + 7][lcol] = xb.w;
            *(float4*)&v_s[nb][vf][4 * vseg]      = va;
            *(float4*)&v_s[nb][vf + 16][4 * vseg] = vb;
            xsq += xa.x * xa.x * sa.x + xa.y * xa.y * sa.y
                 + xa.z * xa.z * sa.z + xa.w * xa.w * sa.w
                 + xb.x * xb.x * sb.x + xb.y * xb.y * sb.y
                 + xb.z * xb.z * sb.z + xb.w * xb.w * sb.w;
        }
        __syncthreads();
    }

    // ---- epilogue ----
    // xsq partials: 4 contributors per row (lq 0..3)
    xsq_s[lq][lrow] = xsq;
    __syncthreads();

    // per-thread: sum over its 4 k of xv^2, per row; then reduce over tx (16 lanes)
    float rs[4];
#pragma unroll
    for (int i = 0; i < 4; i++) {
        float p = acc[i][0] * acc[i][0] + acc[i][1] * acc[i][1]
                + acc[i][2] * acc[i][2] + acc[i][3] * acc[i][3];
#pragma unroll
        for (int m = 1; m < 16; m <<= 1)
            p += __shfl_xor_sync(0xffffffffu, p, m);
        rs[i] = p;
    }

    if (tx == 0) {
#pragma unroll
        for (int i = 0; i < 4; i++) {
            const int r = 4 * ty + i;
            float xst = xsq_s[0][r] + xsq_s[1][r] + xsq_s[2][r] + xsq_s[3][r];
            out[row0 + r] = 0.5f * (rs[i] - xst);
        }
    }
}

extern "C" void kernel_launch(void* const* d_in, const int* in_sizes, int n_in,
                              void* d_out, int out_size) {
    const float* x = (const float*)d_in[0];   // [8192, 4096]
    const float* v = (const float*)d_in[1];   // [4096, 64]
    float* out = (float*)d_out;               // [8192, 1]

    compute_s_kernel<<<Fn / 256, 256>>>(v);
    fm_kernel<<<Bn / TM, NTHREADS>>>(x, v, out);
}

// round 3
// speedup vs baseline: 1.6892x; 1.6892x over previous
#include <cuda_runtime.h>
#include <cstdint>

#define Bn 8192
#define Fn 4096
#define Kn 64
#define MT 64            // rows per CTA -> 128 CTAs
#define KC 32            // F-depth per stage
#define NT 256
#define STAGES 4
#define NTILES (Fn / KC) // 128

#define ROWB 144         // row stride bytes (36 floats = 32 + 4 pad)

// ---- smem layout (bytes) ----
#define SM_S      0                     // s table: 4096 f32 = 16384
#define SM_RED    16384                 // 4 x 64 f32 = 1024
#define SM_XSQ    17408                 // 4 x 64 f32 = 1024
#define SM_TILES  18432
#define SLOT_X    0                     // 64 x 144 = 9216
#define SLOT_VH   9216
#define SLOT_VL   18432
#define SLOT_SZ   27648
#define SMEM_TOTAL (SM_TILES + STAGES * SLOT_SZ)   // 129024

__device__ float d_s[Fn];
__device__ float d_vth[Kn * Fn];   // v^T hi, tf32-exact  [64][4096]
__device__ float d_vtl[Kn * Fn];   // v^T lo, tf32-exact

__device__ __forceinline__ uint32_t smem_u32(const void* p) {
    uint32_t a;
    asm("{ .reg .u64 t; cvta.to.shared.u64 t, %1; cvt.u32.u64 %0, t; }" : "=r"(a) : "l"(p));
    return a;
}
#define CP16(sa, gp) \
    asm volatile("cp.async.cg.shared.global [%0], [%1], 16;" :: "r"(sa), "l"(gp) : "memory")
#define CP_COMMIT() asm volatile("cp.async.commit_group;" ::: "memory")

__device__ __forceinline__ uint32_t to_tf32(float f) {
    uint32_t u;
    asm("cvt.rna.tf32.f32 %0, %1;" : "=r"(u) : "f"(f));
    return u;
}
__device__ __forceinline__ void mma_tf32(float* c, const uint32_t* a,
                                         uint32_t b0, uint32_t b1) {
    asm volatile("mma.sync.aligned.m16n8k8.row.col.f32.tf32.tf32.f32 "
                 "{%0,%1,%2,%3}, {%4,%5,%6,%7}, {%8,%9}, {%0,%1,%2,%3};"
                 : "+f"(c[0]), "+f"(c[1]), "+f"(c[2]), "+f"(c[3])
                 : "r"(a[0]), "r"(a[1]), "r"(a[2]), "r"(a[3]), "r"(b0), "r"(b1));
}

// ================= prep kernels =================
__global__ void prep_s(const float* __restrict__ v) {
    int f = blockIdx.x * blockDim.x + threadIdx.x;
    if (f < Fn) {
        const float4* vp = (const float4*)(v + (size_t)f * Kn);
        float t = 0.f;
#pragma unroll
        for (int k4 = 0; k4 < Kn / 4; k4++) {
            float4 a = vp[k4];
            t += a.x * a.x + a.y * a.y + a.z * a.z + a.w * a.w;
        }
        d_s[f] = t;
    }
}

__global__ void prep_v(const float* __restrict__ v) {
    __shared__ float tile[64][65];
    const int f0 = blockIdx.x * 64;
    const int tid = threadIdx.x;
    for (int i = tid; i < 64 * 64; i += 256) {
        int fr = i >> 6, k = i & 63;
        tile[fr][k] = v[(size_t)(f0 + fr) * Kn + k];
    }
    __syncthreads();
    for (int i = tid; i < 64 * 64; i += 256) {
        int k = i >> 6, fr = i & 63;
        float val = tile[fr][k];
        float hi = __uint_as_float(to_tf32(val));
        float lo = __uint_as_float(to_tf32(val - hi));
        d_vth[(size_t)k * Fn + f0 + fr] = hi;
        d_vtl[(size_t)k * Fn + f0 + fr] = lo;
    }
}

// ================= main kernel =================
__device__ __forceinline__ void load_stage(const float* __restrict__ x, int row0,
                                           int t, uint32_t sb) {
    const int slot = t & (STAGES - 1);
    const int f0 = t * KC;
    const uint32_t base = sb + SM_TILES + slot * SLOT_SZ;
    const int tid = threadIdx.x;
#pragma unroll
    for (int i = 0; i < 2; i++) {
        int id = tid + NT * i;                  // 0..511
        int r = id >> 3, c = id & 7;
        uint32_t off = (uint32_t)(r * ROWB + c * 16);
        CP16(base + SLOT_X + off, x + (size_t)(row0 + r) * Fn + f0 + c * 4);
        CP16(base + SLOT_VH + off, d_vth + (size_t)r * Fn + f0 + c * 4);
        CP16(base + SLOT_VL + off, d_vtl + (size_t)r * Fn + f0 + c * 4);
    }
}

__global__ void __launch_bounds__(NT, 1) fm_kernel(const float* __restrict__ x,
                                                   float* __restrict__ out) {
    extern __shared__ char smem[];
    const uint32_t sb = smem_u32(smem);
    const int tid = threadIdx.x;
    const int warp = tid >> 5, lane = tid & 31;
    const int wm = warp >> 2;        // 0..1  -> M offset 32*wm
    const int wn = warp & 3;         // 0..3  -> N offset 16*wn
    const int lr = lane >> 2, lc = lane & 3;
    const int row0 = blockIdx.x * MT;

    // stage s table
    {
        const float4* sg = (const float4*)d_s;
        float4* ss = (float4*)(smem + SM_S);
        for (int i = tid; i < Fn / 4; i += NT) ss[i] = sg[i];
    }

    // preload stages 0..2
    for (int t = 0; t < STAGES - 1; t++) { load_stage(x, row0, t, sb); CP_COMMIT(); }

    float acc[2][2][4];
#pragma unroll
    for (int a = 0; a < 2; a++)
#pragma unroll
        for (int b = 0; b < 2; b++)
#pragma unroll
            for (int c = 0; c < 4; c++) acc[a][b][c] = 0.f;
    float xsq = 0.f;

    // per-thread fragment byte offsets within a slot
    const uint32_t aoff = (uint32_t)((32 * wm + lr) * ROWB + lc * 4);
    const uint32_t boff = (uint32_t)((16 * wn + lr) * ROWB + lc * 4);
    const int xr = tid >> 2, xq = tid & 3;   // xsq mapping

    for (int t = 0; t < NTILES; t++) {
        const int slot = t & (STAGES - 1);
        if (t + STAGES - 1 < NTILES) asm volatile("cp.async.wait_group 2;" ::: "memory");
        else                         asm volatile("cp.async.wait_group 0;" ::: "memory");
        __syncthreads();
        if (t + STAGES - 1 < NTILES) { load_stage(x, row0, t + STAGES - 1, sb); CP_COMMIT(); }

        const char* tileb = smem + SM_TILES + slot * SLOT_SZ;
        const char* xb  = tileb + SLOT_X;
        const char* vhb = tileb + SLOT_VH;
        const char* vlb = tileb + SLOT_VL;

        // ---- x^2 * s term (exact fp32) ----
        {
            const char* xrow = xb + xr * ROWB + xq * 32;
            float4 x0 = *(const float4*)(xrow);
            float4 x1 = *(const float4*)(xrow + 16);
            const char* srow = smem + SM_S + (t * KC + xq * 8) * 4;
            float4 s0 = *(const float4*)(srow);
            float4 s1 = *(const float4*)(srow + 16);
            xsq += x0.x * x0.x * s0.x + x0.y * x0.y * s0.y
                 + x0.z * x0.z * s0.z + x0.w * x0.w * s0.w
                 + x1.x * x1.x * s1.x + x1.y * x1.y * s1.y
                 + x1.z * x1.z * s1.z + x1.w * x1.w * s1.w;
        }

        // ---- MMA: 4 k-steps of 8 ----
#pragma unroll
        for (int ks = 0; ks < 4; ks++) {
            uint32_t ar[2][4];
#pragma unroll
            for (int mt = 0; mt < 2; mt++) {
                const char* ab = xb + aoff + mt * (16 * ROWB) + ks * 32;
                ar[mt][0] = to_tf32(*(const float*)(ab));
                ar[mt][1] = to_tf32(*(const float*)(ab + 8 * ROWB));
                ar[mt][2] = to_tf32(*(const float*)(ab + 16));
                ar[mt][3] = to_tf32(*(const float*)(ab + 8 * ROWB + 16));
            }
#pragma unroll
            for (int nt = 0; nt < 2; nt++) {
                const char* bh = vhb + boff + nt * (8 * ROWB) + ks * 32;
                uint32_t bh0 = *(const uint32_t*)(bh);
                uint32_t bh1 = *(const uint32_t*)(bh + 16);
                mma_tf32(acc[0][nt], ar[0], bh0, bh1);
                mma_tf32(acc[1][nt], ar[1], bh0, bh1);
                const char* bl = vlb + boff + nt * (8 * ROWB) + ks * 32;
                uint32_t bl0 = *(const uint32_t*)(bl);
                uint32_t bl1 = *(const uint32_t*)(bl + 16);
                mma_tf32(acc[0][nt], ar[0], bl0, bl1);
                mma_tf32(acc[1][nt], ar[1], bl0, bl1);
            }
        }
    }

    // ---- epilogue ----
    ((float*)(smem + SM_XSQ))[xq * 64 + xr] = xsq;

    float* red = (float*)(smem + SM_RED);
#pragma unroll
    for (int mt = 0; mt < 2; mt++) {
        float p0 = acc[mt][0][0] * acc[mt][0][0] + acc[mt][0][1] * acc[mt][0][1]
                 + acc[mt][1][0] * acc[mt][1][0] + acc[mt][1][1] * acc[mt][1][1];
        float p1 = acc[mt][0][2] * acc[mt][0][2] + acc[mt][0][3] * acc[mt][0][3]
                 + acc[mt][1][2] * acc[mt][1][2] + acc[mt][1][3] * acc[mt][1][3];
        p0 += __shfl_xor_sync(0xffffffffu, p0, 1);
        p0 += __shfl_xor_sync(0xffffffffu, p0, 2);
        p1 += __shfl_xor_sync(0xffffffffu, p1, 1);
        p1 += __shfl_xor_sync(0xffffffffu, p1, 2);
        if (lc == 0) {
            int r = 32 * wm + 16 * mt + lr;
            red[wn * 64 + r] = p0;
            red[wn * 64 + r + 8] = p1;
        }
    }
    __syncthreads();

    if (tid < MT) {
        float tot = red[tid] + red[64 + tid] + red[128 + tid] + red[192 + tid];
        const float* xs = (const float*)(smem + SM_XSQ);
        float xst = xs[tid] + xs[64 + tid] + xs[128 + tid] + xs[192 + tid];
        out[row0 + tid] = 0.5f * (tot - xst);
    }
}

extern "C" void kernel_launch(void* const* d_in, const int* in_sizes, int n_in,
                              void* d_out, int out_size) {
    const float* x = (const float*)d_in[0];   // [8192, 4096]
    const float* v = (const float*)d_in[1];   // [4096, 64]
    float* out = (float*)d_out;               // [8192, 1]

    cudaFuncSetAttribute(fm_kernel, cudaFuncAttributeMaxDynamicSharedMemorySize, SMEM_TOTAL);
    prep_s<<<Fn / 256, 256>>>(v);
    prep_v<<<Fn / 64, 256>>>(v);
    fm_kernel<<<Bn / MT, NT, SMEM_TOTAL>>>(x, out);
}